// round 9
// baseline (speedup 1.0000x reference)
#include <cuda_runtime.h>
#include <math.h>

#define N_POINTS   4194304
#define NUM_LEVELS 16
#define HASH_MASK  ((1u << 19) - 1u)
#define THREADS    1024
#define CTAS       148
#define NQUADS     (N_POINTS / 16)    // warp-iterations: 16 points each

struct Params {
    float rm1[NUM_LEVELS];
    int   res0, res1, n0, ncells;     // dense-cache dims for levels 0,1
};

extern __shared__ float2 s_tab[];     // [res0^3 + res1^3] dense level-0/1 cache

__device__ __forceinline__ unsigned hash3(float fx, float fy, float fz, float rm1) {
    return (((unsigned)(fx * rm1))
         ^  ((unsigned)(fy * rm1) * 2654435761u)
         ^  ((unsigned)(fz * rm1) * 805459861u)) & HASH_MASK;
}

__global__ __launch_bounds__(THREADS, 1)
void hashenc_kernel(const float*  __restrict__ pts,
                    const float*  __restrict__ tables,
                    float*        __restrict__ out,
                    Params pp)
{
    const float2* tb = reinterpret_cast<const float2*>(tables);

    // ---- Build dense smem cache for levels 0,1 (once per persistent CTA).
    for (int c = threadIdx.x; c < pp.ncells; c += THREADS) {
        int lvl, cc, r;
        if (c < pp.n0) { lvl = 0; cc = c;         r = pp.res0; }
        else           { lvl = 1; cc = c - pp.n0; r = pp.res1; }
        const unsigned cz  = (unsigned)(cc % r);
        const unsigned tmp = (unsigned)(cc / r);
        const unsigned cy  = tmp % (unsigned)r;
        const unsigned cx  = tmp / (unsigned)r;
        const unsigned h = (cx ^ (cy * 2654435761u) ^ (cz * 805459861u)) & HASH_MASK;
        s_tab[c] = __ldcg(tb + ((size_t)lvl << 19) + h);
    }
    __syncthreads();

    const int t     = threadIdx.x;
    const int lane  = t & 31;
    const int lpair = lane & 7;                  // level pair 0..7
    const int sub   = lane >> 3;                 // point-within-group 0..3
    const int gw    = blockIdx.x * (THREADS >> 5) + (t >> 5);
    const int gstep = CTAS * (THREADS >> 5);

    const float r0f = pp.rm1[0], r1f = pp.rm1[1];
    const int   r0  = pp.res0,   r1  = pp.res1;
    const int   l0  = lpair * 2, l1 = l0 + 1;
    const float ra  = pp.rm1[l0], rb = pp.rm1[l1];
    const float2* tA = tb + ((size_t)l0 << 19);
    const float2* tB = tb + ((size_t)l1 << 19);

    for (int gp = gw; gp < NQUADS; gp += gstep) {
        const size_t pbase = (size_t)gp * 16;

        // ---- Phase 1: all 12 broadcast point loads + normalize (independent).
        float fx[4], fy[4], fz[4];
        #pragma unroll
        for (int u = 0; u < 4; ++u) {
            const size_t p = pbase + (size_t)u * 4 + sub;
            const float x = __ldcs(pts + 3 * p + 0);
            const float y = __ldcs(pts + 3 * p + 1);
            const float z = __ldcs(pts + 3 * p + 2);
            fx[u] = fminf(fmaxf((x + 1.0f) * 0.5f, 0.0f), 1.0f);
            fy[u] = fminf(fmaxf((y + 1.0f) * 0.5f, 0.0f), 1.0f);
            fz[u] = fminf(fmaxf((z + 1.0f) * 0.5f, 0.0f), 1.0f);
        }

        // ---- Phase 2: 8 independent lookups per thread (LDS for lpair 0,
        //      LDG for lpairs 1..7), all issued before any consumption.
        float2 f0[4], f1[4];
        if (lpair == 0) {
            #pragma unroll
            for (int u = 0; u < 4; ++u) {
                const int i0 = ((int)(fx[u]*r0f) * r0 + (int)(fy[u]*r0f)) * r0 + (int)(fz[u]*r0f);
                const int i1 = ((int)(fx[u]*r1f) * r1 + (int)(fy[u]*r1f)) * r1 + (int)(fz[u]*r1f);
                f0[u] = s_tab[i0];
                f1[u] = s_tab[pp.n0 + i1];
            }
        } else if (lpair < 3) {            // levels 2..5: small, keep L1
            #pragma unroll
            for (int u = 0; u < 4; ++u) {
                f0[u] = __ldg(tA + hash3(fx[u], fy[u], fz[u], ra));
                f1[u] = __ldg(tB + hash3(fx[u], fy[u], fz[u], rb));
            }
        } else {                            // levels 6..15: bypass L1
            #pragma unroll
            for (int u = 0; u < 4; ++u) {
                f0[u] = __ldcg(tA + hash3(fx[u], fy[u], fz[u], ra));
                f1[u] = __ldcg(tB + hash3(fx[u], fy[u], fz[u], rb));
            }
        }

        // ---- Phase 3: 4 coalesced 512B warp stores, streaming.
        float4* ob = reinterpret_cast<float4*>(out);
        #pragma unroll
        for (int u = 0; u < 4; ++u) {
            const size_t p = pbase + (size_t)u * 4 + sub;
            __stcs(ob + p * 8 + lpair,
                   make_float4(f0[u].x, f0[u].y, f1[u].x, f1[u].y));
        }
    }
}

extern "C" void kernel_launch(void* const* d_in, const int* in_sizes, int n_in,
                              void* d_out, int out_size)
{
    (void)in_sizes; (void)n_in; (void)out_size;

    // numpy-identical resolution computation (double precision, same op order)
    Params pp;
    int res[NUM_LEVELS];
    const double l128 = log(128.0);
    for (int i = 0; i < NUM_LEVELS; ++i) {
        res[i] = (int)floor(16.0 * exp(((double)i * l128) / 15.0));
        pp.rm1[i] = (float)(res[i] - 1);
    }
    pp.res0   = res[0];
    pp.res1   = res[1];
    pp.n0     = res[0] * res[0] * res[0];
    pp.ncells = pp.n0 + res[1] * res[1] * res[1];

    const size_t smem_bytes = (size_t)pp.ncells * sizeof(float2);
    cudaFuncSetAttribute(hashenc_kernel,
                         cudaFuncAttributeMaxDynamicSharedMemorySize,
                         (int)smem_bytes);

    const float* pts    = (const float*)d_in[0];
    const float* tables = (const float*)d_in[1];
    float*       out    = (float*)d_out;

    hashenc_kernel<<<CTAS, THREADS, smem_bytes>>>(pts, tables, out, pp);
}

// round 10
// speedup vs baseline: 1.0581x; 1.0581x over previous
#include <cuda_runtime.h>
#include <math.h>

#define N_POINTS   4194304
#define NUM_LEVELS 16
#define HASH_MASK  ((1u << 19) - 1u)
#define BLOCK      256

// Per-level (res-1), host-computed with numpy-identical double math, passed by
// value (constant bank; baked into the captured graph).
struct ResParams { float rm1[NUM_LEVELS]; };

__device__ __forceinline__ unsigned hash3(float fx, float fy, float fz, float rm1) {
    return (((unsigned)(fx * rm1))
         ^  ((unsigned)(fy * rm1) * 2654435761u)
         ^  ((unsigned)(fz * rm1) * 805459861u)) & HASH_MASK;
}

// Flat kernel, no smem, no persistence (max occupancy) — the R6 layout with a
// x2 point unroll (R8's only validated improvement): warp = 8 points, thread
// = (point sub, level pair) over two groups -> 4 independent gathers/thread.
__global__ __launch_bounds__(BLOCK)
void hashenc_kernel(const float*  __restrict__ pts,
                    const float*  __restrict__ tables,
                    float*        __restrict__ out,
                    ResParams rp)
{
    const int t     = threadIdx.x;
    const int lane  = t & 31;
    const int lpair = lane & 7;                  // level pair 0..7
    const int sub   = lane >> 3;                 // point-within-group 0..3
    const int gw    = blockIdx.x * (BLOCK >> 5) + (t >> 5);   // warp id

    const size_t pA = (size_t)gw * 8 + sub;      // first group's point
    const size_t pB = pA + 4;                    // second group's point

    // Broadcast point loads (8 lanes/point). Default caching: each 128B line
    // of pts serves ~2.7 consecutive warps -> L1 reuse.
    const float xA = __ldg(pts + 3 * pA + 0);
    const float yA = __ldg(pts + 3 * pA + 1);
    const float zA = __ldg(pts + 3 * pA + 2);
    const float xB = __ldg(pts + 3 * pB + 0);
    const float yB = __ldg(pts + 3 * pB + 1);
    const float zB = __ldg(pts + 3 * pB + 2);

    // normalize [-1,1] -> [0,1], clamp (matches jnp.clip((p+1)*0.5, 0, 1))
    const float fxA = fminf(fmaxf((xA + 1.0f) * 0.5f, 0.0f), 1.0f);
    const float fyA = fminf(fmaxf((yA + 1.0f) * 0.5f, 0.0f), 1.0f);
    const float fzA = fminf(fmaxf((zA + 1.0f) * 0.5f, 0.0f), 1.0f);
    const float fxB = fminf(fmaxf((xB + 1.0f) * 0.5f, 0.0f), 1.0f);
    const float fyB = fminf(fmaxf((yB + 1.0f) * 0.5f, 0.0f), 1.0f);
    const float fzB = fminf(fmaxf((zB + 1.0f) * 0.5f, 0.0f), 1.0f);

    const int l0 = lpair * 2;
    const int l1 = l0 + 1;
    const float ra = rp.rm1[l0];
    const float rb = rp.rm1[l1];

    const float2* tA = reinterpret_cast<const float2*>(tables) + ((size_t)l0 << 19);
    const float2* tB = reinterpret_cast<const float2*>(tables) + ((size_t)l1 << 19);

    // 4 independent gathers per thread. Coarse levels (0-5) keep L1;
    // fine levels (6-15) bypass L1 (.cg) so they don't thrash coarse entries.
    float2 f0A, f1A, f0B, f1B;
    if (lpair < 3) {
        f0A = __ldg (tA + hash3(fxA, fyA, fzA, ra));
        f1A = __ldg (tB + hash3(fxA, fyA, fzA, rb));
        f0B = __ldg (tA + hash3(fxB, fyB, fzB, ra));
        f1B = __ldg (tB + hash3(fxB, fyB, fzB, rb));
    } else {
        f0A = __ldcg(tA + hash3(fxA, fyA, fzA, ra));
        f1A = __ldcg(tB + hash3(fxA, fyA, fzA, rb));
        f0B = __ldcg(tA + hash3(fxB, fyB, fzB, ra));
        f1B = __ldcg(tB + hash3(fxB, fyB, fzB, rb));
    }

    // Two coalesced 512B warp stores (streaming: output written once).
    float4* ob = reinterpret_cast<float4*>(out);
    __stcs(ob + pA * 8 + lpair, make_float4(f0A.x, f0A.y, f1A.x, f1A.y));
    __stcs(ob + pB * 8 + lpair, make_float4(f0B.x, f0B.y, f1B.x, f1B.y));
}

extern "C" void kernel_launch(void* const* d_in, const int* in_sizes, int n_in,
                              void* d_out, int out_size)
{
    (void)in_sizes; (void)n_in; (void)out_size;

    // numpy-identical resolution computation (double precision, same op order)
    ResParams rp;
    const double l128 = log(128.0);
    for (int i = 0; i < NUM_LEVELS; ++i) {
        const int res = (int)floor(16.0 * exp(((double)i * l128) / 15.0));
        rp.rm1[i] = (float)(res - 1);
    }

    const float* pts    = (const float*)d_in[0];
    const float* tables = (const float*)d_in[1];
    float*       out    = (float*)d_out;

    // one warp per 8 points -> N_POINTS*4 threads
    const long long total = (long long)N_POINTS * 4;
    hashenc_kernel<<<(unsigned)(total / BLOCK), BLOCK>>>(pts, tables, out, rp);
}

// round 11
// speedup vs baseline: 1.0846x; 1.0251x over previous
#include <cuda_runtime.h>
#include <math.h>

#define N_POINTS   4194304
#define NUM_LEVELS 16
#define HASH_MASK  ((1u << 19) - 1u)
#define BLOCK      256

// Per-level (res-1), host-computed with numpy-identical double math, passed by
// value (constant bank; baked into the captured graph).
struct ResParams { float rm1[NUM_LEVELS]; };

__device__ __forceinline__ unsigned hash3(float fx, float fy, float fz, float rm1) {
    return (((unsigned)(fx * rm1))
         ^  ((unsigned)(fy * rm1) * 2654435761u)
         ^  ((unsigned)(fz * rm1) * 805459861u)) & HASH_MASK;
}

// R10 layout (warp = 8 points, thread = (sub, lpair), 4 independent gathers)
// + cooperative point load: ONE 96B LDG (lanes 0-23) + 6 SHFLs replaces six
// broadcast LDGs (~9 L1tex wavefronts -> ~2 + shuffle-unit work).
__global__ __launch_bounds__(BLOCK)
void hashenc_kernel(const float*  __restrict__ pts,
                    const float*  __restrict__ tables,
                    float*        __restrict__ out,
                    ResParams rp)
{
    const int t     = threadIdx.x;
    const int lane  = t & 31;
    const int lpair = lane & 7;                  // level pair 0..7
    const int sub   = lane >> 3;                 // point-within-group 0..3
    const int gw    = blockIdx.x * (BLOCK >> 5) + (t >> 5);   // warp id

    const size_t pA = (size_t)gw * 8 + sub;      // group-A point
    const size_t pB = pA + 4;                    // group-B point

    // Cooperative point load: warp's 8 points = 96 contiguous bytes.
    float v = 0.0f;
    if (lane < 24) v = __ldcs(pts + (size_t)gw * 24 + lane);
    const float xA = __shfl_sync(0xffffffffu, v, 3 * sub + 0);
    const float yA = __shfl_sync(0xffffffffu, v, 3 * sub + 1);
    const float zA = __shfl_sync(0xffffffffu, v, 3 * sub + 2);
    const float xB = __shfl_sync(0xffffffffu, v, 12 + 3 * sub + 0);
    const float yB = __shfl_sync(0xffffffffu, v, 12 + 3 * sub + 1);
    const float zB = __shfl_sync(0xffffffffu, v, 12 + 3 * sub + 2);

    // normalize [-1,1] -> [0,1], clamp (matches jnp.clip((p+1)*0.5, 0, 1))
    const float fxA = fminf(fmaxf((xA + 1.0f) * 0.5f, 0.0f), 1.0f);
    const float fyA = fminf(fmaxf((yA + 1.0f) * 0.5f, 0.0f), 1.0f);
    const float fzA = fminf(fmaxf((zA + 1.0f) * 0.5f, 0.0f), 1.0f);
    const float fxB = fminf(fmaxf((xB + 1.0f) * 0.5f, 0.0f), 1.0f);
    const float fyB = fminf(fmaxf((yB + 1.0f) * 0.5f, 0.0f), 1.0f);
    const float fzB = fminf(fmaxf((zB + 1.0f) * 0.5f, 0.0f), 1.0f);

    const int l0 = lpair * 2;
    const int l1 = l0 + 1;
    const float ra = rp.rm1[l0];
    const float rb = rp.rm1[l1];

    const float2* tA = reinterpret_cast<const float2*>(tables) + ((size_t)l0 << 19);
    const float2* tB = reinterpret_cast<const float2*>(tables) + ((size_t)l1 << 19);

    // 4 independent gathers per thread. Coarse levels (0-5) keep L1;
    // fine levels (6-15) bypass L1 (.cg) so they don't thrash coarse entries.
    float2 f0A, f1A, f0B, f1B;
    if (lpair < 3) {
        f0A = __ldg (tA + hash3(fxA, fyA, fzA, ra));
        f1A = __ldg (tB + hash3(fxA, fyA, fzA, rb));
        f0B = __ldg (tA + hash3(fxB, fyB, fzB, ra));
        f1B = __ldg (tB + hash3(fxB, fyB, fzB, rb));
    } else {
        f0A = __ldcg(tA + hash3(fxA, fyA, fzA, ra));
        f1A = __ldcg(tB + hash3(fxA, fyA, fzA, rb));
        f0B = __ldcg(tA + hash3(fxB, fyB, fzB, ra));
        f1B = __ldcg(tB + hash3(fxB, fyB, fzB, rb));
    }

    // Two coalesced 512B warp stores (streaming: output written once).
    float4* ob = reinterpret_cast<float4*>(out);
    __stcs(ob + pA * 8 + lpair, make_float4(f0A.x, f0A.y, f1A.x, f1A.y));
    __stcs(ob + pB * 8 + lpair, make_float4(f0B.x, f0B.y, f1B.x, f1B.y));
}

extern "C" void kernel_launch(void* const* d_in, const int* in_sizes, int n_in,
                              void* d_out, int out_size)
{
    (void)in_sizes; (void)n_in; (void)out_size;

    // numpy-identical resolution computation (double precision, same op order)
    ResParams rp;
    const double l128 = log(128.0);
    for (int i = 0; i < NUM_LEVELS; ++i) {
        const int res = (int)floor(16.0 * exp(((double)i * l128) / 15.0));
        rp.rm1[i] = (float)(res - 1);
    }

    const float* pts    = (const float*)d_in[0];
    const float* tables = (const float*)d_in[1];
    float*       out    = (float*)d_out;

    // one warp per 8 points -> N_POINTS*4 threads
    const long long total = (long long)N_POINTS * 4;
    hashenc_kernel<<<(unsigned)(total / BLOCK), BLOCK>>>(pts, tables, out, rp);
}